// round 15
// baseline (speedup 1.0000x reference)
#include <cuda_runtime.h>
#include <cuda_fp16.h>
#include <math.h>
#include <stdint.h>

#define LNUM 8
#define DMODEL 512
#define DINX 1024
#define DSX 16
#define SLEN 256
#define TTOT 512   // BATCH * SLEN tokens

// ---------------- scratch (static device memory; no allocations) ----------------
__device__ float g_meanp[128 * 768];
__device__ float g_hidden[TTOT * DMODEL];
__device__ float g_resid[TTOT * DMODEL];
__device__ float g_xnorm[TTOT * DMODEL];
__device__ float g_xz[TTOT * 2 * DINX];
__device__ float g_dt[TTOT * DINX];
__device__ float g_y[TTOT * DINX];
__device__ float g_g[TTOT * 2 * DINX];
__device__ float g_Aneg[LNUM * DINX * DSX];
__device__ float g_part[4 * TTOT * DMODEL];   // split-K partial slab (4 MB)
__device__ float g_la[128];

__device__ __forceinline__ float siluf(float x) { return x / (1.0f + __expf(-x)); }
__device__ __forceinline__ float softplusf(float x) {
    return fmaxf(x, 0.0f) + log1pf(__expf(-fabsf(x)));
}

// ---- warp-level fp16 HMMA (sm_80+ PTX; tensor-core path that compiles for sm_103) ----
__device__ __forceinline__ void mma16816(float* c, const uint32_t* a, const uint32_t* b) {
    asm volatile(
        "mma.sync.aligned.m16n8k16.row.col.f32.f16.f16.f32 "
        "{%0,%1,%2,%3}, {%4,%5,%6,%7}, {%8,%9}, {%0,%1,%2,%3};"
        : "+f"(c[0]), "+f"(c[1]), "+f"(c[2]), "+f"(c[3])
        : "r"(a[0]), "r"(a[1]), "r"(a[2]), "r"(a[3]), "r"(b[0]), "r"(b[1]));
}

__device__ __forceinline__ void ldsm_x4(uint32_t* r, uint32_t addr) {
    asm volatile(
        "ldmatrix.sync.aligned.m8n8.x4.shared.b16 {%0,%1,%2,%3}, [%4];"
        : "=r"(r[0]), "=r"(r[1]), "=r"(r[2]), "=r"(r[3]) : "r"(addr));
}

__device__ __forceinline__ uint32_t s2u(const void* p) {
    uint32_t a;
    asm("{ .reg .u64 t; cvta.to.shared.u64 t, %1; cvt.u32.u64 %0, t; }" : "=r"(a) : "l"(p));
    return a;
}

// ====== HMMA GEMM: C[M,N] = A[M,K] @ W[N,K]^T ======
// fp32 accuracy via fp16 hi/lo split of BOTH operands; 3 MMA passes (hh, lh, hl).
// BK=32, double-buffered dynamic smem, register prefetch, LDSM fragment loads.
// AOP: 0 = A[m*lda+k]; 1 = gate y*silu(z); 2 = glu g1*silu(g2);
//      3 = sum of 8 split-K partials (g_part, [z][512][64]);
//      4 = fused causal-conv+silu of g_xz (A param = conv_w, bias param = conv_b)
// EPI: 0 plain store (ldc), 2 softplus(+bias), 4 split-K partial -> g_part
#define SKB 40
#define GSMEM (4 * 2 * 64 * SKB * 2)   // 81920 B

template <int AOP, int EPI>
__global__ void __launch_bounds__(256, 2)
mma_gemm(const float* __restrict__ A, int lda,
         const float* __restrict__ W, int ldb,
         const float* __restrict__ bias,
         float* __restrict__ C, int ldc, int kSpan)
{
    extern __shared__ __half smh[];
    auto sp = [&](int arr, int buf, int row, int k) -> __half* {
        return smh + ((size_t)((arr * 2 + buf) * 64 + row)) * SKB + k;
    };

    const int tid = threadIdx.x;
    const int wid = tid >> 5, lane = tid & 31;
    const int wm = wid >> 1, wn = wid & 1;
    const int grp = lane >> 2, tq = lane & 3;

    const int m0 = blockIdx.y * 64;
    const int n0 = blockIdx.x * 64;
    const int kBase = blockIdx.z * kSpan;
    const int nChunks = kSpan >> 5;

    float acc[4][4];
#pragma unroll
    for (int j = 0; j < 4; j++)
#pragma unroll
        for (int q = 0; q < 4; q++) acc[j][q] = 0.f;

    const int row = tid >> 2;
    const int kq = (tid & 3) * 8;

    auto loadA = [&](int m, int k) -> float4 {
        if constexpr (AOP == 0) {
            return *(const float4*)(A + (size_t)m * lda + k);
        } else if constexpr (AOP == 1) {
            float4 y = *(const float4*)(g_y + (size_t)m * DINX + k);
            float4 z = *(const float4*)(g_xz + (size_t)m * 2048 + 1024 + k);
            return make_float4(y.x * siluf(z.x), y.y * siluf(z.y),
                               y.z * siluf(z.z), y.w * siluf(z.w));
        } else if constexpr (AOP == 2) {
            float4 a = *(const float4*)(g_g + (size_t)m * 2048 + k);
            float4 b = *(const float4*)(g_g + (size_t)m * 2048 + 1024 + k);
            return make_float4(a.x * siluf(b.x), a.y * siluf(b.y),
                               a.z * siluf(b.z), a.w * siluf(b.w));
        } else if constexpr (AOP == 3) {
            float4 s = make_float4(0.f, 0.f, 0.f, 0.f);
#pragma unroll
            for (int z = 0; z < 8; z++) {
                float4 p = *(const float4*)(g_part + (size_t)z * 32768 + m * 64 + k);
                s.x += p.x; s.y += p.y; s.z += p.z; s.w += p.w;
            }
            return s;
        } else {
            // AOP==4: xc[m, k..k+3] = silu(conv(xz)); A = conv_w, bias = conv_b
            const int sstep = m & 255;
            const float4 cw0 = *(const float4*)(A + (k + 0) * 4);
            const float4 cw1 = *(const float4*)(A + (k + 1) * 4);
            const float4 cw2 = *(const float4*)(A + (k + 2) * 4);
            const float4 cw3 = *(const float4*)(A + (k + 3) * 4);
            float4 r = *(const float4*)(bias + k);
#pragma unroll
            for (int j = 0; j < 4; j++) {
                if (sstep - 3 + j >= 0) {
                    float4 xz4 = *(const float4*)(g_xz + (size_t)(m - 3 + j) * 2048 + k);
                    const float w0 = j == 0 ? cw0.x : j == 1 ? cw0.y : j == 2 ? cw0.z : cw0.w;
                    const float w1 = j == 0 ? cw1.x : j == 1 ? cw1.y : j == 2 ? cw1.z : cw1.w;
                    const float w2 = j == 0 ? cw2.x : j == 1 ? cw2.y : j == 2 ? cw2.z : cw2.w;
                    const float w3 = j == 0 ? cw3.x : j == 1 ? cw3.y : j == 2 ? cw3.z : cw3.w;
                    r.x = fmaf(w0, xz4.x, r.x);
                    r.y = fmaf(w1, xz4.y, r.y);
                    r.z = fmaf(w2, xz4.z, r.z);
                    r.w = fmaf(w3, xz4.w, r.w);
                }
            }
            return make_float4(siluf(r.x), siluf(r.y), siluf(r.z), siluf(r.w));
        }
    };

    float4 rgA[2], rgB[2];
    auto fetch = [&](int c) {
        const int k = kBase + c * 32 + kq;
        rgA[0] = loadA(m0 + row, k);
        rgA[1] = loadA(m0 + row, k + 4);
        rgB[0] = *(const float4*)(W + (size_t)(n0 + row) * ldb + k);
        rgB[1] = *(const float4*)(W + (size_t)(n0 + row) * ldb + k + 4);
    };
    auto split8 = [&](const float4* v2, int arrH, int arrL, int buf) {
#pragma unroll
        for (int i = 0; i < 2; i++) {
            const float4 v = v2[i];
            const float vv[4] = {v.x, v.y, v.z, v.w};
            union { __half h[4]; uint2 u; } H, L;
#pragma unroll
            for (int q = 0; q < 4; q++) {
                __half h = __float2half_rn(vv[q]);
                H.h[q] = h;
                L.h[q] = __float2half_rn(vv[q] - __half2float(h));
            }
            *(uint2*)sp(arrH, buf, row, kq + i * 4) = H.u;
            *(uint2*)sp(arrL, buf, row, kq + i * 4) = L.u;
        }
    };
    auto store = [&](int buf) {
        split8(rgA, 0, 1, buf);
        split8(rgB, 2, 3, buf);
    };

    const int lr8 = lane & 7, lt = lane >> 3;
    const int rowA = wm * 16 + (lt & 1) * 8 + lr8;
    const int kA = (lt >> 1) * 8;
    const int colB = wn * 32 + (lt >> 1) * 8 + lr8;
    const int kB = (lt & 1) * 8;
    const uint32_t smbase = s2u(smh);
    const uint32_t BUFSTR = 64 * SKB * 2;
    auto baseoff = [&](int arr, int r, int k) -> uint32_t {
        return smbase + (uint32_t)(((arr * 2) * 64 + r) * SKB + k) * 2;
    };
    const uint32_t aAh = baseoff(0, rowA, kA);
    const uint32_t aAl = baseoff(1, rowA, kA);
    const uint32_t aBh0 = baseoff(2, colB, kB);
    const uint32_t aBh1 = baseoff(2, colB + 16, kB);
    const uint32_t aBl0 = baseoff(3, colB, kB);
    const uint32_t aBl1 = baseoff(3, colB + 16, kB);

    fetch(0);
    store(0);
    if (nChunks > 1) fetch(1);
    __syncthreads();

    for (int c = 0; c < nChunks; c++) {
        const int buf = c & 1;
        const uint32_t bo = buf * BUFSTR;
        if (c + 1 < nChunks) {
            store(buf ^ 1);
            if (c + 2 < nChunks) fetch(c + 2);
        }
#pragma unroll
        for (int ks = 0; ks < 2; ks++) {
            const uint32_t ko2 = ks * 32;
            uint32_t Ah[4], Al[4], Bh[2][4], Bl[2][4];
            ldsm_x4(Ah, aAh + bo + ko2);
            ldsm_x4(Al, aAl + bo + ko2);
            ldsm_x4(Bh[0], aBh0 + bo + ko2);
            ldsm_x4(Bh[1], aBh1 + bo + ko2);
            ldsm_x4(Bl[0], aBl0 + bo + ko2);
            ldsm_x4(Bl[1], aBl1 + bo + ko2);
#pragma unroll
            for (int p = 0; p < 2; p++)
#pragma unroll
                for (int j = 0; j < 2; j++) {
                    const int nt = p * 2 + j;
                    mma16816(acc[nt], Ah, &Bh[p][2 * j]);
                    mma16816(acc[nt], Al, &Bh[p][2 * j]);
                    mma16816(acc[nt], Ah, &Bl[p][2 * j]);
                }
        }
        __syncthreads();
    }

    const int Nt = gridDim.x * 64;
    const int Mt = gridDim.y * 64;
#pragma unroll
    for (int nt = 0; nt < 4; nt++) {
        const int col = n0 + wn * 32 + nt * 8 + 2 * tq;
#pragma unroll
        for (int half = 0; half < 2; half++) {
            const int r = m0 + wm * 16 + grp + half * 8;
            float v0 = acc[nt][half * 2 + 0];
            float v1 = acc[nt][half * 2 + 1];
            if constexpr (EPI == 2) {
                v0 = softplusf(v0 + bias[col]);
                v1 = softplusf(v1 + bias[col + 1]);
            }
            float2 v = make_float2(v0, v1);
            if constexpr (EPI == 4) {
                *(float2*)(g_part + (size_t)blockIdx.z * Mt * Nt + (size_t)r * Nt + col) = v;
            } else {
                *(float2*)(C + (size_t)r * ldc + col) = v;
            }
        }
    }
}

// ---------------- tokenize ----------------
__global__ void patch_mean_kernel(const float* __restrict__ images)
{
    const int blc = blockIdx.x;
    const int tid = threadIdx.x;
    const int y = tid >> 4, x = tid & 15;
    const int c = blc % 3, bl = blc / 3;
    const float* base = images + (size_t)blc * 224 * 224;
    float s = 0.f;
#pragma unroll 2
    for (int py = 0; py < 14; py++) {
        const float* row = base + (py * 16 + y) * 224 + x;
#pragma unroll
        for (int px = 0; px < 14; px++) s += row[px * 16];
    }
    g_meanp[(size_t)bl * 768 + c * 256 + tid] = s * (1.0f / 196.0f);
}

// img token = patch_b + sum of 4 patch-GEMM partials (reduce_bias fused here)
__global__ void token_kernel(const float* __restrict__ patch_b,
                             const float* __restrict__ states,
                             const float* __restrict__ state_w, const float* __restrict__ state_b,
                             const float* __restrict__ actions,
                             const float* __restrict__ act_w, const float* __restrict__ act_b)
{
    const int bl = blockIdx.x;
    const int d = threadIdx.x;
    const int b = bl >> 6, li = bl & 63;
    const int base = b * SLEN + li * 4;

    float iv = patch_b[d];
#pragma unroll
    for (int z = 0; z < 4; z++) iv += g_part[(size_t)z * 65536 + bl * 512 + d];
    g_hidden[(size_t)(base + 0) * DMODEL + d] = iv;

    const float* st = states + (size_t)bl * 3 * 7;
    float s = state_b[d];
#pragma unroll
    for (int j = 0; j < 7; j++) s = fmaf(st[j], state_w[d * 7 + j], s);
    g_hidden[(size_t)(base + 1) * DMODEL + d] = s;

#pragma unroll
    for (int t = 0; t < 2; t++) {
        const float* ac = actions + (size_t)(bl * 3 + t) * 4;
        float a = act_b[d];
#pragma unroll
        for (int j = 0; j < 4; j++) a = fmaf(ac[j], act_w[d * 4 + j], a);
        g_hidden[(size_t)(base + 2 + t) * DMODEL + d] = a;
    }
}

__global__ void aneg_kernel(const float* __restrict__ A_log)
{
    int i = blockIdx.x * 256 + threadIdx.x;
    if (i < LNUM * DINX * DSX) g_Aneg[i] = -expf(A_log[i]);
}

// residual += hidden (g_hidden if NS==0 / layer-0 zero-resid; else NS partials + resid)
// float2-vectorized: thread t handles elements [2t, 2t+1].
template <int NS>
__global__ void add_rms_kernel(const float* __restrict__ w)
{
    const int t = blockIdx.x;
    const int tid = threadIdx.x;      // 256
    const size_t base = (size_t)t * DMODEL;
    float2 a;
    if (NS == 0) {
        a = *(const float2*)(g_hidden + base + 2 * tid);
    } else {
        a = make_float2(0.f, 0.f);
#pragma unroll
        for (int z = 0; z < NS; z++) {
            float2 p = *(const float2*)(g_part + (size_t)z * TTOT * DMODEL + base + 2 * tid);
            a.x += p.x; a.y += p.y;
        }
        float2 r = *(const float2*)(g_resid + base + 2 * tid);
        a.x += r.x; a.y += r.y;
    }
    *(float2*)(g_resid + base + 2 * tid) = a;
    float ss = a.x * a.x + a.y * a.y;
#pragma unroll
    for (int off = 16; off; off >>= 1) ss += __shfl_xor_sync(0xffffffffu, ss, off);
    __shared__ float red[8];
    if ((tid & 31) == 0) red[tid >> 5] = ss;
    __syncthreads();
    float tot = red[0] + red[1] + red[2] + red[3] + red[4] + red[5] + red[6] + red[7];
    float sc = rsqrtf(tot * (1.0f / 512.0f) + 1e-5f);
    float2 wv = *(const float2*)(w + 2 * tid);
    *(float2*)(g_xnorm + base + 2 * tid) = make_float2(a.x * sc * wv.x, a.y * sc * wv.y);
}

// ---------------- selective scan (conv + partial-reduce fused into staging) ----------------
// Grid (64, 2), block 256 = 16 d-channels x 16 states.
__global__ void scan_kernel(int l, const float* __restrict__ Dp_l,
                            const float* __restrict__ cw, const float* __restrict__ cb)
{
    const int b = blockIdx.y;
    const int d0 = blockIdx.x << 4;
    const int tid = threadIdx.x;
    const int d = tid >> 4, n = tid & 15;
    const float Aa = g_Aneg[((size_t)l * DINX + d0 + d) * DSX + n];
    const float Dv = Dp_l[d0 + d];

    __shared__ float sdt[2][32][16], sxc[2][32][16], sBt[2][32][16], sCt[2][32][16];

    const int ls = tid >> 4, ld = tid & 15;   // staging: step ls/(ls+16), channel ld
    const float4 cwv = *(const float4*)(cw + (d0 + ld) * 4);
    const float cbv = cb[d0 + ld];

    float r0[4], r1[4];
    auto convAt = [&](int sstep) -> float {
        const int t = (b << 8) + sstep;
        float a = cbv;
        if (sstep - 3 >= 0) a = fmaf(cwv.x, g_xz[(size_t)(t - 3) * 2048 + d0 + ld], a);
        if (sstep - 2 >= 0) a = fmaf(cwv.y, g_xz[(size_t)(t - 2) * 2048 + d0 + ld], a);
        if (sstep - 1 >= 0) a = fmaf(cwv.z, g_xz[(size_t)(t - 1) * 2048 + d0 + ld], a);
        a = fmaf(cwv.w, g_xz[(size_t)t * 2048 + d0 + ld], a);
        return siluf(a);
    };
    auto sumPart = [&](int t, int col) -> float {
        float s = 0.f;
#pragma unroll
        for (int z = 0; z < 8; z++) s += g_part[(size_t)z * 32768 + t * 64 + col];
        return s;
    };
    auto fetchT = [&](int tile) {
        const int s0 = (tile << 5) + ls;
        const int t0 = (b << 8) + s0;
        r0[0] = g_dt[(size_t)t0 * DINX + d0 + ld];
        r0[1] = convAt(s0);
        r0[2] = sumPart(t0, 32 + ld);
        r0[3] = sumPart(t0, 48 + ld);
        r1[0] = g_dt[(size_t)(t0 + 16) * DINX + d0 + ld];
        r1[1] = convAt(s0 + 16);
        r1[2] = sumPart(t0 + 16, 32 + ld);
        r1[3] = sumPart(t0 + 16, 48 + ld);
    };
    auto commitT = [&](int buf) {
        sdt[buf][ls][ld] = r0[0]; sxc[buf][ls][ld] = r0[1];
        sBt[buf][ls][ld] = r0[2]; sCt[buf][ls][ld] = r0[3];
        sdt[buf][ls + 16][ld] = r1[0]; sxc[buf][ls + 16][ld] = r1[1];
        sBt[buf][ls + 16][ld] = r1[2]; sCt[buf][ls + 16][ld] = r1[3];
    };

    fetchT(0); commitT(0);
    fetchT(1);
    __syncthreads();

    float h = 0.f;
    for (int tile = 0; tile < 8; tile++) {
        const int buf = tile & 1;
        const int t0 = (b << 8) + (tile << 5);
#pragma unroll 8
        for (int s = 0; s < 32; s++) {
            float dtv = sdt[buf][s][d];
            float xv  = sxc[buf][s][d];
            float Bn  = sBt[buf][s][n];
            float Cn  = sCt[buf][s][n];
            float a = __expf(dtv * Aa);
            h = fmaf(a, h, dtv * Bn * xv);
            float c = h * Cn;
            c += __shfl_down_sync(0xffffffffu, c, 8, 16);
            c += __shfl_down_sync(0xffffffffu, c, 4, 16);
            c += __shfl_down_sync(0xffffffffu, c, 2, 16);
            c += __shfl_down_sync(0xffffffffu, c, 1, 16);
            if (n == 0) g_y[(size_t)(t0 + s) * DINX + d0 + d] = fmaf(Dv, xv, c);
        }
        __syncthreads();
        if (tile + 1 < 8) {
            commitT((tile + 1) & 1);
            if (tile + 2 < 8) fetchT(tile + 2);
            __syncthreads();
        }
    }
}

// ---------------- head + loss ----------------
__global__ void head_kernel(const float* __restrict__ head_w, const float* __restrict__ head_b,
                            const float* __restrict__ labels,
                            float* __restrict__ out, int ofs, int write_preds)
{
    const int bl = blockIdx.x;
    const int w = threadIdx.x >> 5;
    const int lane = threadIdx.x & 31;
    const int t = w >> 2, a = w & 3;
    const int b = bl >> 6, li = bl & 63;
    const int tok = b * SLEN + li * 4 + 1 + t;
    const float* x = g_xnorm + (size_t)tok * DMODEL;
    const float* hw = head_w + a * DMODEL;
    float s = 0.f;
    for (int i = lane; i < DMODEL; i += 32) s = fmaf(x[i], hw[i], s);
#pragma unroll
    for (int off = 16; off; off >>= 1) s += __shfl_xor_sync(0xffffffffu, s, off);
    __shared__ float sd[12];
    if (lane == 0) {
        float pred = s + head_b[a];
        int idx = bl * 12 + t * 4 + a;
        if (write_preds) out[ofs + idx] = pred;
        sd[w] = fabsf(pred - labels[idx]);
    }
    __syncthreads();
    if (threadIdx.x == 0) {
        float acc = 0.f;
#pragma unroll
        for (int i = 0; i < 12; i++) acc += sd[i];
        g_la[bl] = acc * (1.0f / 12.0f);
    }
}

__global__ void loss_kernel(const int* __restrict__ seqlen, float* __restrict__ out, int write_loss)
{
    const int tid = threadIdx.x;
    const int b = tid >> 6, li = tid & 63;
    float m = (li < seqlen[b]) ? 1.f : 0.f;
    __shared__ float sv[128], sm[128];
    sv[tid] = g_la[tid] * m;
    sm[tid] = m;
    __syncthreads();
    if (tid == 0 && write_loss) {
        float s0 = 0, c0 = 0, s1 = 0, c1 = 0;
        for (int i = 0; i < 64; i++) { s0 += sv[i]; c0 += sm[i]; s1 += sv[64 + i]; c1 += sm[64 + i]; }
        float l0 = s0 / fmaxf(c0, 1.f);
        float l1 = s1 / fmaxf(c1, 1.f);
        out[0] = 0.5f * (l0 + l1);
    }
}

// ---------------- host ----------------
extern "C" void kernel_launch(void* const* d_in, const int* in_sizes, int n_in,
                              void* d_out, int out_size)
{
    const float* images   = (const float*)d_in[0];
    const int*   seqlen   = (const int*)  d_in[1];
    const float* states   = (const float*)d_in[2];
    const float* actions  = (const float*)d_in[3];
    const float* labels   = (const float*)d_in[4];
    const float* patch_w  = (const float*)d_in[5];
    const float* patch_b  = (const float*)d_in[6];
    const float* state_w  = (const float*)d_in[7];
    const float* state_b  = (const float*)d_in[8];
    const float* act_w    = (const float*)d_in[9];
    const float* act_b    = (const float*)d_in[10];
    const float* norm1_w  = (const float*)d_in[11];
    const float* in_proj_w= (const float*)d_in[12];
    const float* conv_w   = (const float*)d_in[13];
    const float* conv_b   = (const float*)d_in[14];
    const float* x_proj_w = (const float*)d_in[15];
    const float* dt_w     = (const float*)d_in[16];
    const float* dt_b     = (const float*)d_in[17];
    const float* A_log    = (const float*)d_in[18];
    const float* Dp       = (const float*)d_in[19];
    const float* out_proj_w=(const float*)d_in[20];
    const float* norm2_w  = (const float*)d_in[21];
    const float* fc1_w    = (const float*)d_in[22];
    const float* fc2_w    = (const float*)d_in[23];
    const float* norm_f_w = (const float*)d_in[24];
    const float* head_w   = (const float*)d_in[25];
    const float* head_b   = (const float*)d_in[26];
    float* out = (float*)d_out;

    float *p_meanp, *p_xnorm, *p_xz, *p_dt, *p_g;
    cudaGetSymbolAddress((void**)&p_meanp, g_meanp);
    cudaGetSymbolAddress((void**)&p_xnorm, g_xnorm);
    cudaGetSymbolAddress((void**)&p_xz, g_xz);
    cudaGetSymbolAddress((void**)&p_dt, g_dt);
    cudaGetSymbolAddress((void**)&p_g, g_g);

    cudaFuncSetAttribute(mma_gemm<0,0>, cudaFuncAttributeMaxDynamicSharedMemorySize, GSMEM);
    cudaFuncSetAttribute(mma_gemm<0,4>, cudaFuncAttributeMaxDynamicSharedMemorySize, GSMEM);
    cudaFuncSetAttribute(mma_gemm<1,4>, cudaFuncAttributeMaxDynamicSharedMemorySize, GSMEM);
    cudaFuncSetAttribute(mma_gemm<2,4>, cudaFuncAttributeMaxDynamicSharedMemorySize, GSMEM);
    cudaFuncSetAttribute(mma_gemm<3,2>, cudaFuncAttributeMaxDynamicSharedMemorySize, GSMEM);
    cudaFuncSetAttribute(mma_gemm<4,4>, cudaFuncAttributeMaxDynamicSharedMemorySize, GSMEM);

    // prologue
    aneg_kernel<<<(LNUM * DINX * DSX + 255) / 256, 256>>>(A_log);
    patch_mean_kernel<<<384, 256>>>(images);
    // img token partials: [128,512] = meanp[128,768] @ patch_w^T  (split-K 4)
    mma_gemm<0,4><<<dim3(8, 2, 4), 256, GSMEM>>>(p_meanp, 768, patch_w, 768,
                                                 nullptr, nullptr, 512, 192);
    token_kernel<<<128, 512>>>(patch_b, states, state_w, state_b, actions, act_w, act_b);

    for (int l = 0; l < LNUM; l++) {
        if (l == 0) add_rms_kernel<0><<<TTOT, 256>>>(norm1_w);
        else        add_rms_kernel<2><<<TTOT, 256>>>(norm1_w + l * DMODEL);
        // xz[512,2048] = xnorm @ in_proj^T (K=512)
        mma_gemm<0,0><<<dim3(32, 8, 1), 256, GSMEM>>>(p_xnorm, 512,
            in_proj_w + (size_t)l * 2048 * 512, 512, nullptr, p_xz, 2048, 512);
        // proj partials[8][512,64] = conv(xz) @ x_proj^T (conv fused in A-load; split-K 8)
        mma_gemm<4,4><<<dim3(1, 8, 8), 256, GSMEM>>>(conv_w + (size_t)l * DINX * 4, 0,
            x_proj_w + (size_t)l * 64 * 1024, 1024, conv_b + l * DINX, nullptr, 64, 128);
        // dt[512,1024] = softplus(sum(partials)[:, :32] @ dt_w^T + dt_b) (reduce fused in A)
        mma_gemm<3,2><<<dim3(16, 8, 1), 256, GSMEM>>>(nullptr, 0,
            dt_w + (size_t)l * 1024 * 32, 32, dt_b + l * DINX, p_dt, 1024, 32);
        // scan (conv + B/C partial-reduce fused into staging)
        scan_kernel<<<dim3(64, 2), 256>>>(l, Dp + l * DINX,
            conv_w + (size_t)l * DINX * 4, conv_b + l * DINX);
        // hidden_partials = (y*silu(z)) @ out_proj^T (split-K 2, gate fused in A)
        mma_gemm<1,4><<<dim3(8, 8, 2), 256, GSMEM>>>(nullptr, 0,
            out_proj_w + (size_t)l * 512 * 1024, 1024, nullptr, nullptr, 512, 512);
        add_rms_kernel<2><<<TTOT, 256>>>(norm2_w + l * DMODEL);
        // g[512,2048] = xnorm @ fc1^T (K=512)
        mma_gemm<0,0><<<dim3(32, 8, 1), 256, GSMEM>>>(p_xnorm, 512,
            fc1_w + (size_t)l * 2048 * 512, 512, nullptr, p_g, 2048, 512);
        // hidden_partials = (g1*silu(g2)) @ fc2^T (split-K 2, GLU fused in A)
        mma_gemm<2,4><<<dim3(8, 8, 2), 256, GSMEM>>>(nullptr, 0,
            fc2_w + (size_t)l * 512 * 1024, 1024, nullptr, nullptr, 512, 512);
    }

    // final norm + head + loss
    add_rms_kernel<2><<<TTOT, 256>>>(norm_f_w);
    int write_preds = (out_size >= 1536) ? 1 : 0;
    int ofs = (out_size == 1536) ? 0 : 1;
    int write_loss = (out_size != 1536) ? 1 : 0;
    head_kernel<<<128, 384>>>(head_w, head_b, labels, out, ofs, write_preds);
    loss_kernel<<<1, 128>>>(seqlen, out, write_loss);
}

// round 17
// speedup vs baseline: 1.1375x; 1.1375x over previous
#include <cuda_runtime.h>
#include <cuda_fp16.h>
#include <math.h>
#include <stdint.h>

#define LNUM 8
#define DMODEL 512
#define DINX 1024
#define DSX 16
#define SLEN 256
#define TTOT 512   // BATCH * SLEN tokens

// ---------------- scratch (static device memory; no allocations) ----------------
__device__ float g_meanp[128 * 768];
__device__ float g_hidden[TTOT * DMODEL];
__device__ float g_resid[TTOT * DMODEL];
__device__ float g_xnorm[TTOT * DMODEL];
__device__ float g_xz[TTOT * 2 * DINX];
__device__ float g_dt[TTOT * DINX];
__device__ float g_y[TTOT * DINX];
__device__ float g_g[TTOT * 2 * DINX];
__device__ float g_Aneg[LNUM * DINX * DSX];
__device__ float g_part[4 * TTOT * DMODEL];   // split-K partial slab (4 MB)
__device__ float g_la[128];

__device__ __forceinline__ float siluf(float x) { return x / (1.0f + __expf(-x)); }
__device__ __forceinline__ float softplusf(float x) {
    return fmaxf(x, 0.0f) + log1pf(__expf(-fabsf(x)));
}

// ---- warp-level fp16 HMMA (sm_80+ PTX; tensor-core path that compiles for sm_103) ----
__device__ __forceinline__ void mma16816(float* c, const uint32_t* a, const uint32_t* b) {
    asm volatile(
        "mma.sync.aligned.m16n8k16.row.col.f32.f16.f16.f32 "
        "{%0,%1,%2,%3}, {%4,%5,%6,%7}, {%8,%9}, {%0,%1,%2,%3};"
        : "+f"(c[0]), "+f"(c[1]), "+f"(c[2]), "+f"(c[3])
        : "r"(a[0]), "r"(a[1]), "r"(a[2]), "r"(a[3]), "r"(b[0]), "r"(b[1]));
}

__device__ __forceinline__ void ldsm_x4(uint32_t* r, uint32_t addr) {
    asm volatile(
        "ldmatrix.sync.aligned.m8n8.x4.shared.b16 {%0,%1,%2,%3}, [%4];"
        : "=r"(r[0]), "=r"(r[1]), "=r"(r[2]), "=r"(r[3]) : "r"(addr));
}

__device__ __forceinline__ uint32_t s2u(const void* p) {
    uint32_t a;
    asm("{ .reg .u64 t; cvta.to.shared.u64 t, %1; cvt.u32.u64 %0, t; }" : "=r"(a) : "l"(p));
    return a;
}

// ====== HMMA GEMM: C[M,N] = A[M,K] @ W[N,K]^T ======
// fp32 accuracy via fp16 hi/lo split of BOTH operands; 3 MMA passes (hh, lh, hl).
// BK=32, double-buffered dynamic smem, register prefetch, LDSM fragment loads.
// SKB=40 (80 B row stride: 16B-aligned rows for LDSM + conflict-free banks 20r mod 32).
// AOP: 0 = A[m*lda+k]; 1 = gate y*silu(z); 2 = glu g1*silu(g2);
//      3 = sum of 8 split-K partials (g_part, [z][512][64]);
//      4 = fused causal-conv+silu of g_xz (A param = conv_w, bias param = conv_b)
// EPI: 0 plain store (ldc), 2 softplus(+bias), 4 split-K partial -> g_part
#define SKB 40
#define GSMEM (4 * 2 * 64 * SKB * 2)   // 81920 B

template <int AOP, int EPI>
__global__ void __launch_bounds__(256, 2)
mma_gemm(const float* __restrict__ A, int lda,
         const float* __restrict__ W, int ldb,
         const float* __restrict__ bias,
         float* __restrict__ C, int ldc, int kSpan)
{
    extern __shared__ __half smh[];
    auto sp = [&](int arr, int buf, int row, int k) -> __half* {
        return smh + ((size_t)((arr * 2 + buf) * 64 + row)) * SKB + k;
    };

    const int tid = threadIdx.x;
    const int wid = tid >> 5, lane = tid & 31;
    const int wm = wid >> 1, wn = wid & 1;
    const int grp = lane >> 2, tq = lane & 3;

    const int m0 = blockIdx.y * 64;
    const int n0 = blockIdx.x * 64;
    const int kBase = blockIdx.z * kSpan;
    const int nChunks = kSpan >> 5;

    float acc[4][4];
#pragma unroll
    for (int j = 0; j < 4; j++)
#pragma unroll
        for (int q = 0; q < 4; q++) acc[j][q] = 0.f;

    const int row = tid >> 2;
    const int kq = (tid & 3) * 8;

    auto loadA = [&](int m, int k) -> float4 {
        if constexpr (AOP == 0) {
            return *(const float4*)(A + (size_t)m * lda + k);
        } else if constexpr (AOP == 1) {
            float4 y = *(const float4*)(g_y + (size_t)m * DINX + k);
            float4 z = *(const float4*)(g_xz + (size_t)m * 2048 + 1024 + k);
            return make_float4(y.x * siluf(z.x), y.y * siluf(z.y),
                               y.z * siluf(z.z), y.w * siluf(z.w));
        } else if constexpr (AOP == 2) {
            float4 a = *(const float4*)(g_g + (size_t)m * 2048 + k);
            float4 b = *(const float4*)(g_g + (size_t)m * 2048 + 1024 + k);
            return make_float4(a.x * siluf(b.x), a.y * siluf(b.y),
                               a.z * siluf(b.z), a.w * siluf(b.w));
        } else if constexpr (AOP == 3) {
            float4 s = make_float4(0.f, 0.f, 0.f, 0.f);
#pragma unroll
            for (int z = 0; z < 8; z++) {
                float4 p = *(const float4*)(g_part + (size_t)z * 32768 + m * 64 + k);
                s.x += p.x; s.y += p.y; s.z += p.z; s.w += p.w;
            }
            return s;
        } else {
            // AOP==4: xc[m, k..k+3] = silu(conv(xz)); A = conv_w, bias = conv_b
            const int sstep = m & 255;
            const float4 cw0 = *(const float4*)(A + (k + 0) * 4);
            const float4 cw1 = *(const float4*)(A + (k + 1) * 4);
            const float4 cw2 = *(const float4*)(A + (k + 2) * 4);
            const float4 cw3 = *(const float4*)(A + (k + 3) * 4);
            float4 r = *(const float4*)(bias + k);
#pragma unroll
            for (int j = 0; j < 4; j++) {
                if (sstep - 3 + j >= 0) {
                    float4 xz4 = *(const float4*)(g_xz + (size_t)(m - 3 + j) * 2048 + k);
                    const float w0 = j == 0 ? cw0.x : j == 1 ? cw0.y : j == 2 ? cw0.z : cw0.w;
                    const float w1 = j == 0 ? cw1.x : j == 1 ? cw1.y : j == 2 ? cw1.z : cw1.w;
                    const float w2 = j == 0 ? cw2.x : j == 1 ? cw2.y : j == 2 ? cw2.z : cw2.w;
                    const float w3 = j == 0 ? cw3.x : j == 1 ? cw3.y : j == 2 ? cw3.z : cw3.w;
                    r.x = fmaf(w0, xz4.x, r.x);
                    r.y = fmaf(w1, xz4.y, r.y);
                    r.z = fmaf(w2, xz4.z, r.z);
                    r.w = fmaf(w3, xz4.w, r.w);
                }
            }
            return make_float4(siluf(r.x), siluf(r.y), siluf(r.z), siluf(r.w));
        }
    };

    float4 rgA[2], rgB[2];
    auto fetch = [&](int c) {
        const int k = kBase + c * 32 + kq;
        rgA[0] = loadA(m0 + row, k);
        rgA[1] = loadA(m0 + row, k + 4);
        rgB[0] = *(const float4*)(W + (size_t)(n0 + row) * ldb + k);
        rgB[1] = *(const float4*)(W + (size_t)(n0 + row) * ldb + k + 4);
    };
    auto split8 = [&](const float4* v2, int arrH, int arrL, int buf) {
#pragma unroll
        for (int i = 0; i < 2; i++) {
            const float4 v = v2[i];
            const float vv[4] = {v.x, v.y, v.z, v.w};
            union { __half h[4]; uint2 u; } H, L;
#pragma unroll
            for (int q = 0; q < 4; q++) {
                __half h = __float2half_rn(vv[q]);
                H.h[q] = h;
                L.h[q] = __float2half_rn(vv[q] - __half2float(h));
            }
            *(uint2*)sp(arrH, buf, row, kq + i * 4) = H.u;
            *(uint2*)sp(arrL, buf, row, kq + i * 4) = L.u;
        }
    };
    auto store = [&](int buf) {
        split8(rgA, 0, 1, buf);
        split8(rgB, 2, 3, buf);
    };

    const int lr8 = lane & 7, lt = lane >> 3;
    const int rowA = wm * 16 + (lt & 1) * 8 + lr8;
    const int kA = (lt >> 1) * 8;
    const int colB = wn * 32 + (lt >> 1) * 8 + lr8;
    const int kB = (lt & 1) * 8;
    const uint32_t smbase = s2u(smh);
    const uint32_t BUFSTR = 64 * SKB * 2;
    auto baseoff = [&](int arr, int r, int k) -> uint32_t {
        return smbase + (uint32_t)(((arr * 2) * 64 + r) * SKB + k) * 2;
    };
    const uint32_t aAh = baseoff(0, rowA, kA);
    const uint32_t aAl = baseoff(1, rowA, kA);
    const uint32_t aBh0 = baseoff(2, colB, kB);
    const uint32_t aBh1 = baseoff(2, colB + 16, kB);
    const uint32_t aBl0 = baseoff(3, colB, kB);
    const uint32_t aBl1 = baseoff(3, colB + 16, kB);

    fetch(0);
    store(0);
    if (nChunks > 1) fetch(1);
    __syncthreads();

    for (int c = 0; c < nChunks; c++) {
        const int buf = c & 1;
        const uint32_t bo = buf * BUFSTR;
        if (c + 1 < nChunks) {
            store(buf ^ 1);
            if (c + 2 < nChunks) fetch(c + 2);
        }
#pragma unroll
        for (int ks = 0; ks < 2; ks++) {
            const uint32_t ko2 = ks * 32;
            uint32_t Ah[4], Al[4], Bh[2][4], Bl[2][4];
            ldsm_x4(Ah, aAh + bo + ko2);
            ldsm_x4(Al, aAl + bo + ko2);
            ldsm_x4(Bh[0], aBh0 + bo + ko2);
            ldsm_x4(Bh[1], aBh1 + bo + ko2);
            ldsm_x4(Bl[0], aBl0 + bo + ko2);
            ldsm_x4(Bl[1], aBl1 + bo + ko2);
#pragma unroll
            for (int p = 0; p < 2; p++)
#pragma unroll
                for (int j = 0; j < 2; j++) {
                    const int nt = p * 2 + j;
                    mma16816(acc[nt], Ah, &Bh[p][2 * j]);
                    mma16816(acc[nt], Al, &Bh[p][2 * j]);
                    mma16816(acc[nt], Ah, &Bl[p][2 * j]);
                }
        }
        __syncthreads();
    }

    const int Nt = gridDim.x * 64;
    const int Mt = gridDim.y * 64;
#pragma unroll
    for (int nt = 0; nt < 4; nt++) {
        const int col = n0 + wn * 32 + nt * 8 + 2 * tq;
#pragma unroll
        for (int half = 0; half < 2; half++) {
            const int r = m0 + wm * 16 + grp + half * 8;
            float v0 = acc[nt][half * 2 + 0];
            float v1 = acc[nt][half * 2 + 1];
            if constexpr (EPI == 2) {
                v0 = softplusf(v0 + bias[col]);
                v1 = softplusf(v1 + bias[col + 1]);
            }
            float2 v = make_float2(v0, v1);
            if constexpr (EPI == 4) {
                *(float2*)(g_part + (size_t)blockIdx.z * Mt * Nt + (size_t)r * Nt + col) = v;
            } else {
                *(float2*)(C + (size_t)r * ldc + col) = v;
            }
        }
    }
}

// ---------------- tokenize ----------------
__global__ void patch_mean_kernel(const float* __restrict__ images)
{
    const int blc = blockIdx.x;
    const int tid = threadIdx.x;
    const int y = tid >> 4, x = tid & 15;
    const int c = blc % 3, bl = blc / 3;
    const float* base = images + (size_t)blc * 224 * 224;
    float s = 0.f;
#pragma unroll 2
    for (int py = 0; py < 14; py++) {
        const float* row = base + (py * 16 + y) * 224 + x;
#pragma unroll
        for (int px = 0; px < 14; px++) s += row[px * 16];
    }
    g_meanp[(size_t)bl * 768 + c * 256 + tid] = s * (1.0f / 196.0f);
}

// img token = patch_b + sum of 4 patch-GEMM partials (reduce_bias fused here)
__global__ void token_kernel(const float* __restrict__ patch_b,
                             const float* __restrict__ states,
                             const float* __restrict__ state_w, const float* __restrict__ state_b,
                             const float* __restrict__ actions,
                             const float* __restrict__ act_w, const float* __restrict__ act_b)
{
    const int bl = blockIdx.x;
    const int d = threadIdx.x;
    const int b = bl >> 6, li = bl & 63;
    const int base = b * SLEN + li * 4;

    float iv = patch_b[d];
#pragma unroll
    for (int z = 0; z < 4; z++) iv += g_part[(size_t)z * 65536 + bl * 512 + d];
    g_hidden[(size_t)(base + 0) * DMODEL + d] = iv;

    const float* st = states + (size_t)bl * 3 * 7;
    float s = state_b[d];
#pragma unroll
    for (int j = 0; j < 7; j++) s = fmaf(st[j], state_w[d * 7 + j], s);
    g_hidden[(size_t)(base + 1) * DMODEL + d] = s;

#pragma unroll
    for (int t = 0; t < 2; t++) {
        const float* ac = actions + (size_t)(bl * 3 + t) * 4;
        float a = act_b[d];
#pragma unroll
        for (int j = 0; j < 4; j++) a = fmaf(ac[j], act_w[d * 4 + j], a);
        g_hidden[(size_t)(base + 2 + t) * DMODEL + d] = a;
    }
}

__global__ void aneg_kernel(const float* __restrict__ A_log)
{
    int i = blockIdx.x * 256 + threadIdx.x;
    if (i < LNUM * DINX * DSX) g_Aneg[i] = -expf(A_log[i]);
}

// residual += hidden (g_hidden if NS==0 / layer-0 zero-resid; else NS partials + resid)
// float2-vectorized: thread t handles elements [2t, 2t+1].
template <int NS>
__global__ void add_rms_kernel(const float* __restrict__ w)
{
    const int t = blockIdx.x;
    const int tid = threadIdx.x;      // 256
    const size_t base = (size_t)t * DMODEL;
    float2 a;
    if (NS == 0) {
        a = *(const float2*)(g_hidden + base + 2 * tid);
    } else {
        a = make_float2(0.f, 0.f);
#pragma unroll
        for (int z = 0; z < NS; z++) {
            float2 p = *(const float2*)(g_part + (size_t)z * TTOT * DMODEL + base + 2 * tid);
            a.x += p.x; a.y += p.y;
        }
        float2 r = *(const float2*)(g_resid + base + 2 * tid);
        a.x += r.x; a.y += r.y;
    }
    *(float2*)(g_resid + base + 2 * tid) = a;
    float ss = a.x * a.x + a.y * a.y;
#pragma unroll
    for (int off = 16; off; off >>= 1) ss += __shfl_xor_sync(0xffffffffu, ss, off);
    __shared__ float red[8];
    if ((tid & 31) == 0) red[tid >> 5] = ss;
    __syncthreads();
    float tot = red[0] + red[1] + red[2] + red[3] + red[4] + red[5] + red[6] + red[7];
    float sc = rsqrtf(tot * (1.0f / 512.0f) + 1e-5f);
    float2 wv = *(const float2*)(w + 2 * tid);
    *(float2*)(g_xnorm + base + 2 * tid) = make_float2(a.x * sc * wv.x, a.y * sc * wv.y);
}

// ---------------- selective scan (conv + partial-reduce fused into staging) ----------------
// Grid (64, 2), block 256 = 16 d-channels x 16 states.
__global__ void scan_kernel(int l, const float* __restrict__ Dp_l,
                            const float* __restrict__ cw, const float* __restrict__ cb)
{
    const int b = blockIdx.y;
    const int d0 = blockIdx.x << 4;
    const int tid = threadIdx.x;
    const int d = tid >> 4, n = tid & 15;
    const float Aa = g_Aneg[((size_t)l * DINX + d0 + d) * DSX + n];
    const float Dv = Dp_l[d0 + d];

    __shared__ float sdt[2][32][16], sxc[2][32][16], sBt[2][32][16], sCt[2][32][16];

    const int ls = tid >> 4, ld = tid & 15;   // staging: step ls/(ls+16), channel ld
    const float4 cwv = *(const float4*)(cw + (d0 + ld) * 4);
    const float cbv = cb[d0 + ld];

    float r0[4], r1[4];
    auto convAt = [&](int sstep) -> float {
        const int t = (b << 8) + sstep;
        float a = cbv;
        if (sstep - 3 >= 0) a = fmaf(cwv.x, g_xz[(size_t)(t - 3) * 2048 + d0 + ld], a);
        if (sstep - 2 >= 0) a = fmaf(cwv.y, g_xz[(size_t)(t - 2) * 2048 + d0 + ld], a);
        if (sstep - 1 >= 0) a = fmaf(cwv.z, g_xz[(size_t)(t - 1) * 2048 + d0 + ld], a);
        a = fmaf(cwv.w, g_xz[(size_t)t * 2048 + d0 + ld], a);
        return siluf(a);
    };
    auto sumPart = [&](int t, int col) -> float {
        float s = 0.f;
#pragma unroll
        for (int z = 0; z < 8; z++) s += g_part[(size_t)z * 32768 + t * 64 + col];
        return s;
    };
    auto fetchT = [&](int tile) {
        const int s0 = (tile << 5) + ls;
        const int t0 = (b << 8) + s0;
        r0[0] = g_dt[(size_t)t0 * DINX + d0 + ld];
        r0[1] = convAt(s0);
        r0[2] = sumPart(t0, 32 + ld);
        r0[3] = sumPart(t0, 48 + ld);
        r1[0] = g_dt[(size_t)(t0 + 16) * DINX + d0 + ld];
        r1[1] = convAt(s0 + 16);
        r1[2] = sumPart(t0 + 16, 32 + ld);
        r1[3] = sumPart(t0 + 16, 48 + ld);
    };
    auto commitT = [&](int buf) {
        sdt[buf][ls][ld] = r0[0]; sxc[buf][ls][ld] = r0[1];
        sBt[buf][ls][ld] = r0[2]; sCt[buf][ls][ld] = r0[3];
        sdt[buf][ls + 16][ld] = r1[0]; sxc[buf][ls + 16][ld] = r1[1];
        sBt[buf][ls + 16][ld] = r1[2]; sCt[buf][ls + 16][ld] = r1[3];
    };

    fetchT(0); commitT(0);
    fetchT(1);
    __syncthreads();

    float h = 0.f;
    for (int tile = 0; tile < 8; tile++) {
        const int buf = tile & 1;
        const int t0 = (b << 8) + (tile << 5);
#pragma unroll 8
        for (int s = 0; s < 32; s++) {
            float dtv = sdt[buf][s][d];
            float xv  = sxc[buf][s][d];
            float Bn  = sBt[buf][s][n];
            float Cn  = sCt[buf][s][n];
            float a = __expf(dtv * Aa);
            h = fmaf(a, h, dtv * Bn * xv);
            float c = h * Cn;
            c += __shfl_down_sync(0xffffffffu, c, 8, 16);
            c += __shfl_down_sync(0xffffffffu, c, 4, 16);
            c += __shfl_down_sync(0xffffffffu, c, 2, 16);
            c += __shfl_down_sync(0xffffffffu, c, 1, 16);
            if (n == 0) g_y[(size_t)(t0 + s) * DINX + d0 + d] = fmaf(Dv, xv, c);
        }
        __syncthreads();
        if (tile + 1 < 8) {
            commitT((tile + 1) & 1);
            if (tile + 2 < 8) fetchT(tile + 2);
            __syncthreads();
        }
    }
}

// ---------------- head + loss ----------------
__global__ void head_kernel(const float* __restrict__ head_w, const float* __restrict__ head_b,
                            const float* __restrict__ labels,
                            float* __restrict__ out, int ofs, int write_preds)
{
    const int bl = blockIdx.x;
    const int w = threadIdx.x >> 5;
    const int lane = threadIdx.x & 31;
    const int t = w >> 2, a = w & 3;
    const int b = bl >> 6, li = bl & 63;
    const int tok = b * SLEN + li * 4 + 1 + t;
    const float* x = g_xnorm + (size_t)tok * DMODEL;
    const float* hw = head_w + a * DMODEL;
    float s = 0.f;
    for (int i = lane; i < DMODEL; i += 32) s = fmaf(x[i], hw[i], s);
#pragma unroll
    for (int off = 16; off; off >>= 1) s += __shfl_xor_sync(0xffffffffu, s, off);
    __shared__ float sd[12];
    if (lane == 0) {
        float pred = s + head_b[a];
        int idx = bl * 12 + t * 4 + a;
        if (write_preds) out[ofs + idx] = pred;
        sd[w] = fabsf(pred - labels[idx]);
    }
    __syncthreads();
    if (threadIdx.x == 0) {
        float acc = 0.f;
#pragma unroll
        for (int i = 0; i < 12; i++) acc += sd[i];
        g_la[bl] = acc * (1.0f / 12.0f);
    }
}

__global__ void loss_kernel(const int* __restrict__ seqlen, float* __restrict__ out, int write_loss)
{
    const int tid = threadIdx.x;
    const int b = tid >> 6, li = tid & 63;
    float m = (li < seqlen[b]) ? 1.f : 0.f;
    __shared__ float sv[128], sm[128];
    sv[tid] = g_la[tid] * m;
    sm[tid] = m;
    __syncthreads();
    if (tid == 0 && write_loss) {
        float s0 = 0, c0 = 0, s1 = 0, c1 = 0;
        for (int i = 0; i < 64; i++) { s0 += sv[i]; c0 += sm[i]; s1 += sv[64 + i]; c1 += sm[64 + i]; }
        float l0 = s0 / fmaxf(c0, 1.f);
        float l1 = s1 / fmaxf(c1, 1.f);
        out[0] = 0.5f * (l0 + l1);
    }
}

// ---------------- host ----------------
extern "C" void kernel_launch(void* const* d_in, const int* in_sizes, int n_in,
                              void* d_out, int out_size)
{
    const float* images   = (const float*)d_in[0];
    const int*   seqlen   = (const int*)  d_in[1];
    const float* states   = (const float*)d_in[2];
    const float* actions  = (const float*)d_in[3];
    const float* labels   = (const float*)d_in[4];
    const float* patch_w  = (const float*)d_in[5];
    const float* patch_b  = (const float*)d_in[6];
    const float* state_w  = (const float*)d_in[7];
    const float* state_b  = (const float*)d_in[8];
    const float* act_w    = (const float*)d_in[9];
    const float* act_b    = (const float*)d_in[10];
    const float* norm1_w  = (const float*)d_in[11];
    const float* in_proj_w= (const float*)d_in[12];
    const float* conv_w   = (const float*)d_in[13];
    const float* conv_b   = (const float*)d_in[14];
    const float* x_proj_w = (const float*)d_in[15];
    const float* dt_w     = (const float*)d_in[16];
    const float* dt_b     = (const float*)d_in[17];
    const float* A_log    = (const float*)d_in[18];
    const float* Dp       = (const float*)d_in[19];
    const float* out_proj_w=(const float*)d_in[20];
    const float* norm2_w  = (const float*)d_in[21];
    const float* fc1_w    = (const float*)d_in[22];
    const float* fc2_w    = (const float*)d_in[23];
    const float* norm_f_w = (const float*)d_in[24];
    const float* head_w   = (const float*)d_in[25];
    const float* head_b   = (const float*)d_in[26];
    float* out = (float*)d_out;

    float *p_meanp, *p_xnorm, *p_xz, *p_dt, *p_g;
    cudaGetSymbolAddress((void**)&p_meanp, g_meanp);
    cudaGetSymbolAddress((void**)&p_xnorm, g_xnorm);
    cudaGetSymbolAddress((void**)&p_xz, g_xz);
    cudaGetSymbolAddress((void**)&p_dt, g_dt);
    cudaGetSymbolAddress((void**)&p_g, g_g);

    cudaFuncSetAttribute(mma_gemm<0,0>, cudaFuncAttributeMaxDynamicSharedMemorySize, GSMEM);
    cudaFuncSetAttribute(mma_gemm<0,4>, cudaFuncAttributeMaxDynamicSharedMemorySize, GSMEM);
    cudaFuncSetAttribute(mma_gemm<1,4>, cudaFuncAttributeMaxDynamicSharedMemorySize, GSMEM);
    cudaFuncSetAttribute(mma_gemm<2,4>, cudaFuncAttributeMaxDynamicSharedMemorySize, GSMEM);
    cudaFuncSetAttribute(mma_gemm<3,2>, cudaFuncAttributeMaxDynamicSharedMemorySize, GSMEM);
    cudaFuncSetAttribute(mma_gemm<4,4>, cudaFuncAttributeMaxDynamicSharedMemorySize, GSMEM);

    // prologue
    aneg_kernel<<<(LNUM * DINX * DSX + 255) / 256, 256>>>(A_log);
    patch_mean_kernel<<<384, 256>>>(images);
    // img token partials: [128,512] = meanp[128,768] @ patch_w^T  (split-K 4)
    mma_gemm<0,4><<<dim3(8, 2, 4), 256, GSMEM>>>(p_meanp, 768, patch_w, 768,
                                                 nullptr, nullptr, 512, 192);
    token_kernel<<<128, 512>>>(patch_b, states, state_w, state_b, actions, act_w, act_b);

    for (int l = 0; l < LNUM; l++) {
        if (l == 0) add_rms_kernel<0><<<TTOT, 256>>>(norm1_w);
        else        add_rms_kernel<4><<<TTOT, 256>>>(norm1_w + l * DMODEL);
        // xz[512,2048] = xnorm @ in_proj^T (K=512)
        mma_gemm<0,0><<<dim3(32, 8, 1), 256, GSMEM>>>(p_xnorm, 512,
            in_proj_w + (size_t)l * 2048 * 512, 512, nullptr, p_xz, 2048, 512);
        // proj partials[8][512,64] = conv(xz) @ x_proj^T (conv fused in A-load; split-K 8)
        mma_gemm<4,4><<<dim3(1, 8, 8), 256, GSMEM>>>(conv_w + (size_t)l * DINX * 4, 0,
            x_proj_w + (size_t)l * 64 * 1024, 1024, conv_b + l * DINX, nullptr, 64, 128);
        // dt[512,1024] = softplus(sum(partials)[:, :32] @ dt_w^T + dt_b) (reduce fused in A)
        mma_gemm<3,2><<<dim3(16, 8, 1), 256, GSMEM>>>(nullptr, 0,
            dt_w + (size_t)l * 1024 * 32, 32, dt_b + l * DINX, p_dt, 1024, 32);
        // scan (conv + B/C partial-reduce fused into staging)
        scan_kernel<<<dim3(64, 2), 256>>>(l, Dp + l * DINX,
            conv_w + (size_t)l * DINX * 4, conv_b + l * DINX);
        // hidden_partials = (y*silu(z)) @ out_proj^T (split-K 4, gate fused in A)
        mma_gemm<1,4><<<dim3(8, 8, 4), 256, GSMEM>>>(nullptr, 0,
            out_proj_w + (size_t)l * 512 * 1024, 1024, nullptr, nullptr, 512, 256);
        add_rms_kernel<4><<<TTOT, 256>>>(norm2_w + l * DMODEL);
        // g[512,2048] = xnorm @ fc1^T (K=512)
        mma_gemm<0,0><<<dim3(32, 8, 1), 256, GSMEM>>>(p_xnorm, 512,
            fc1_w + (size_t)l * 2048 * 512, 512, nullptr, p_g, 2048, 512);
        // hidden_partials = (g1*silu(g2)) @ fc2^T (split-K 4, GLU fused in A)
        mma_gemm<2,4><<<dim3(8, 8, 4), 256, GSMEM>>>(nullptr, 0,
            fc2_w + (size_t)l * 512 * 1024, 1024, nullptr, nullptr, 512, 256);
    }

    // final norm + head + loss
    add_rms_kernel<4><<<TTOT, 256>>>(norm_f_w);
    int write_preds = (out_size >= 1536) ? 1 : 0;
    int ofs = (out_size == 1536) ? 0 : 1;
    int write_loss = (out_size != 1536) ? 1 : 0;
    head_kernel<<<128, 384>>>(head_w, head_b, labels, out, ofs, write_preds);
    loss_kernel<<<1, 128>>>(seqlen, out, write_loss);
}